// round 16
// baseline (speedup 1.0000x reference)
#include <cuda_runtime.h>
#include <math.h>

#define BB 128
#define TT 512
#define WW 64
#define DD 128
#define CC 256
#define KS 12
#define TP 500

typedef unsigned long long ull;
typedef unsigned int uint;

// ---------------- device scratch (no runtime allocation allowed) ----------------
__device__ float g_z[(size_t)BB * TT * DD];        // 33.5 MB  (B,T,D) normalized z
__device__ float g_xp[(size_t)BB * TT * 3 * CC];   // 201 MB   (B,T,768) x_proj
__device__ float g_c[(size_t)BB * TT * CC];        // 67 MB    (B,T,C) GRU hidden states
__device__ float g_whT[3 * CC * CC];               // Wh transposed: [col][k]
__device__ double g_loss;
__device__ int    g_cnt;
__device__ unsigned g_sync[32];                    // [0..15]=cA, [16..31]=cB per rowgroup

__device__ __forceinline__ uint f2tf(float f) {
    uint u;
    asm("cvt.rna.tf32.f32 %0, %1;" : "=r"(u) : "f"(f));
    return u;
}
__device__ __forceinline__ ull ffma2(ull a, ull b, ull c) {
    ull d;
    asm("fma.rn.f32x2 %0, %1, %2, %3;" : "=l"(d) : "l"(a), "l"(b), "l"(c));
    return d;
}
__device__ __forceinline__ ull packf2(float lo, float hi) {
    ull d;
    asm("mov.b64 %0, {%1, %2};" : "=l"(d) : "f"(lo), "f"(hi));
    return d;
}
__device__ __forceinline__ float pairsum(ull v) {
    float lo, hi;
    asm("mov.b64 {%0, %1}, %2;" : "=f"(lo), "=f"(hi) : "l"(v));
    return lo + hi;
}
__device__ __forceinline__ void unpackf2(ull v, float& lo, float& hi) {
    asm("mov.b64 {%0, %1}, %2;" : "=f"(lo), "=f"(hi) : "l"(v));
}
__device__ __forceinline__ void rel_add(unsigned* p) {
    asm volatile("red.release.gpu.global.add.u32 [%0], %1;" :: "l"(p), "r"(1u) : "memory");
}
__device__ __forceinline__ void spin_ge(unsigned* p, unsigned target) {
    unsigned v;
    do {
        asm volatile("ld.acquire.gpu.u32 %0, [%1];" : "=r"(v) : "l"(p) : "memory");
    } while (v < target);
}
#define MMA_TF32(d, a, b) \
    asm volatile("mma.sync.aligned.m16n8k8.row.col.f32.tf32.tf32.f32 " \
                 "{%0,%1,%2,%3},{%4,%5,%6,%7},{%8,%9},{%0,%1,%2,%3};" \
                 : "+f"((d)[0]), "+f"((d)[1]), "+f"((d)[2]), "+f"((d)[3]) \
                 : "r"((a)[0]), "r"((a)[1]), "r"((a)[2]), "r"((a)[3]), \
                   "r"((b)[0]), "r"((b)[1]))

// ---------------- z = l2norm(rr @ We + be)  (+ fused init + Wh transpose) ----------------
__global__ __launch_bounds__(128) void k_z(const float* __restrict__ rr,
                                           const float* __restrict__ We,
                                           const float* __restrict__ be,
                                           const float* __restrict__ Wh) {
    __shared__ float Wes[64 * 128];
    __shared__ float rs[64];
    __shared__ float red[4];
    int b = blockIdx.y;
    int t0 = blockIdx.x << 6;
    int tid = threadIdx.x;

    int gb = blockIdx.y * 8 + blockIdx.x;
    int gtid = gb * 128 + tid;
    if (gtid == 0) {
        g_loss = 0.0; g_cnt = 0;
        for (int i = 0; i < 32; i++) g_sync[i] = 0u;
    }
    for (int i = gtid; i < 3 * CC * CC; i += 131072) {
        int kk = i & 255;
        int col = i >> 8;
        g_whT[i] = Wh[(size_t)kk * 768 + col];
    }

    for (int i = tid; i < 64 * 128; i += 128) Wes[i] = We[i];
    float bias = be[tid];
    __syncthreads();
    for (int tt = 0; tt < 64; tt++) {
        int t = t0 + tt;
        if (tid < 64) rs[tid] = rr[((size_t)b * TT + t) * WW + tid];
        __syncthreads();
        float acc = bias;
#pragma unroll
        for (int w = 0; w < 64; w++) acc += rs[w] * Wes[w * 128 + tid];
        float ss = acc * acc;
#pragma unroll
        for (int o = 16; o; o >>= 1) ss += __shfl_xor_sync(0xffffffffu, ss, o);
        if ((tid & 31) == 0) red[tid >> 5] = ss;
        __syncthreads();
        float tot = red[0] + red[1] + red[2] + red[3];
        float scale = 1.0f / fmaxf(sqrtf(tot), 1e-12f);
        g_z[((size_t)b * TT + t) * DD + tid] = acc * scale;
        __syncthreads();
    }
}

// ---------------- x_proj = z @ Wi + bi  (M=65536, N=768, K=128), FFMA2 ----------------
__global__ __launch_bounds__(256) void k_xproj(const float* __restrict__ Wi,
                                               const float* __restrict__ bi) {
    __shared__ float As[32 * 132];
    __shared__ float Bs[32 * 132];
    int tid = threadIdx.x;
    int tx = tid & 15, ty = tid >> 4;
    int m0 = blockIdx.y << 7, n0 = blockIdx.x << 7;
    ull accp[8][4];
#pragma unroll
    for (int i = 0; i < 8; i++)
#pragma unroll
        for (int p = 0; p < 4; p++) accp[i][p] = 0ull;

    for (int kc = 0; kc < DD; kc += 32) {
        for (int i = tid; i < 4096; i += 256) {
            int r = i >> 5, kk = i & 31;
            As[kk * 132 + r] = g_z[(size_t)(m0 + r) * DD + kc + kk];
        }
        for (int i = tid; i < 4096; i += 256) {
            int kk = i >> 7, n = i & 127;
            Bs[kk * 132 + n] = Wi[(size_t)(kc + kk) * 768 + n0 + n];
        }
        __syncthreads();
#pragma unroll
        for (int kk = 0; kk < 32; kk++) {
            float4 a1 = *(const float4*)&As[kk * 132 + ty * 4];
            float4 a2 = *(const float4*)&As[kk * 132 + 64 + ty * 4];
            ulonglong2 B1 = *(const ulonglong2*)&Bs[kk * 132 + tx * 4];
            ulonglong2 B2 = *(const ulonglong2*)&Bs[kk * 132 + 64 + tx * 4];
            float av[8] = {a1.x, a1.y, a1.z, a1.w, a2.x, a2.y, a2.z, a2.w};
#pragma unroll
            for (int i = 0; i < 8; i++) {
                ull a2i = packf2(av[i], av[i]);
                accp[i][0] = ffma2(a2i, B1.x, accp[i][0]);
                accp[i][1] = ffma2(a2i, B1.y, accp[i][1]);
                accp[i][2] = ffma2(a2i, B2.x, accp[i][2]);
                accp[i][3] = ffma2(a2i, B2.y, accp[i][3]);
            }
        }
        __syncthreads();
    }
#pragma unroll
    for (int i = 0; i < 8; i++) {
        int r = m0 + ((i < 4) ? ty * 4 + i : 64 + ty * 4 + i - 4);
#pragma unroll
        for (int p = 0; p < 4; p++) {
            int j0 = 2 * p;
            float lo, hi;
            unpackf2(accp[i][p], lo, hi);
            int c0 = n0 + ((j0 < 4) ? tx * 4 + j0 : 64 + tx * 4 + j0 - 4);
            g_xp[(size_t)r * 768 + c0]     = lo + bi[c0];
            g_xp[(size_t)r * 768 + c0 + 1] = hi + bi[c0 + 1];
        }
    }
}

// ---------------- dummy: shifts the ncu -s 5 window onto the GRU kernel ----------------
__global__ void k_dummy() {}

// ---------------- split-phase persistent GRU ----------------
// grid (8, 16), 128 CTAs co-resident. Per step, rows 0-3 (phase A) and rows
// 4-7 (phase B) relay through separate counters; each half's L2 relay overlaps
// the other half's compute. WG_H (warps 4-7) updates+releases A and stages the
// next A-half; WG_L (warps 0-3) stages B and updates+releases B. Accumulation
// order per (row, gate, k-octant) identical to R13/R15 -> bit-exact c_seq.
#define GRU4_SMEM ((96 * 256 + 8 * 256 + 4 * 3 * 256) * 4)

#define GRU_PHASE(ROWBASE) do { \
    _Pragma("unroll") \
    for (int r = 0; r < 4; r++) { p0[r] = 0ull; p1[r] = 0ull; p2[r] = 0ull; } \
    _Pragma("unroll") \
    for (int j = 0; j < 8; j++) { \
        int js = j ^ s7; \
        ulonglong2 W0 = ws4[wb0 + js]; \
        ulonglong2 W1 = ws4[wb1 + js]; \
        ulonglong2 W2 = ws4[wb2 + js]; \
        int kofs = kh * 32 + j * 4; \
        _Pragma("unroll") \
        for (int r = 0; r < 4; r++) { \
            ulonglong2 H = *(const ulonglong2*)&hs[(ROWBASE + r) * 256 + kofs]; \
            p0[r] = ffma2(H.x, W0.x, p0[r]); \
            p0[r] = ffma2(H.y, W0.y, p0[r]); \
            p1[r] = ffma2(H.x, W1.x, p1[r]); \
            p1[r] = ffma2(H.y, W1.y, p1[r]); \
            p2[r] = ffma2(H.x, W2.x, p2[r]); \
            p2[r] = ffma2(H.y, W2.y, p2[r]); \
        } \
    } \
    _Pragma("unroll") \
    for (int r = 0; r < 4; r++) { \
        part[(r * 3 + 0) * 256 + kh * 32 + uc] = pairsum(p0[r]); \
        part[(r * 3 + 1) * 256 + kh * 32 + uc] = pairsum(p1[r]); \
        part[(r * 3 + 2) * 256 + kh * 32 + uc] = pairsum(p2[r]); \
    } \
} while (0)

__global__ __launch_bounds__(256, 1) void k_gru4(const float* __restrict__ bh) {
    extern __shared__ float sm[];
    float* ws   = sm;                          // [96 cols][64 float4], XOR-swizzled
    float* hs   = sm + 96 * 256;               // [8][256] h_{t-1} halves
    float* part = sm + 96 * 256 + 8 * 256;     // [4][3][256] per-phase partials

    int tid = threadIdx.x;
    int cgx = blockIdx.x;
    int rg  = blockIdx.y;
    int cb0 = cgx << 5;
    int rb0 = rg << 3;
    unsigned* cA = &g_sync[rg];
    unsigned* cB = &g_sync[16 + rg];

    // ---- load Wh slice once, swizzled ----
    for (int i = tid; i < 96 * 64; i += 256) {
        int bc = i >> 6, kgrp = i & 63;
        int gate = bc >> 5, ch = bc & 31;
        float4 v = *(const float4*)&g_whT[(size_t)(gate * 256 + cb0 + ch) * 256 + kgrp * 4];
        *(float4*)&ws[(bc * 64 + (kgrp ^ (bc & 7))) * 4] = v;
    }
    // ---- zero hs ----
    *(float4*)&hs[tid * 8]     = make_float4(0.f, 0.f, 0.f, 0.f);
    *(float4*)&hs[tid * 8 + 4] = make_float4(0.f, 0.f, 0.f, 0.f);
    __syncthreads();

    int uc = tid & 31;
    int kh = tid >> 5;
    int cg = cb0 + uc;
    bool hi = (kh >= 4);                 // WG_H: warps 4-7
    int lr = kh & 3;                     // local row within phase
    int urow = hi ? lr : lr + 4;         // global row this thread updates
    int b_upd = rb0 + urow;
    float bhr = bh[cg], bhz = bh[256 + cg], bhn = bh[512 + cg];
    const float* xpb = g_xp + (size_t)b_upd * TT * 768;
    float* crow = g_c + (size_t)b_upd * TT * CC;

    // staging: WG_L loads B-half rows 4-7; WG_H loads A-half rows 0-3
    int sflat = (hi ? (tid - 128) : tid) * 8;
    int srow  = (hi ? 0 : 4) + (sflat >> 8);
    int scol  = sflat & 255;
    const float* sbase = g_c + (size_t)(rb0 + srow) * TT * CC + scol;

    const ulonglong2* ws4 = (const ulonglong2*)ws;
    int s7 = uc & 7;
    int wb0 = (0  + uc) * 64 + kh * 8;
    int wb1 = (32 + uc) * 64 + kh * 8;
    int wb2 = (64 + uc) * 64 + kh * 8;

    ull p0[4], p1[4], p2[4];
    float4 stg0, stg1;

    for (int t = 0; t < TT; t++) {
        // §1: WG_L ensures cB(t-1) then loads B-half h_{t-1} into regs
        if (t > 0 && !hi) {
            if (tid == 0) spin_ge(cB, 8u * (unsigned)t);
            asm volatile("bar.sync 1, 128;" ::: "memory");
            const float4* s = (const float4*)(sbase + (size_t)(t - 1) * CC);
            stg0 = __ldcg(s);
            stg1 = __ldcg(s + 1);
        }
        // prefetch x_proj for this thread's update row
        float xr = __ldg(&xpb[(size_t)t * 768 + cg]);
        float xz = __ldg(&xpb[(size_t)t * 768 + 256 + cg]);
        float xn = __ldg(&xpb[(size_t)t * 768 + 512 + cg]);

        // §2: phase A partials (rows 0-3)
        GRU_PHASE(0);
        __syncthreads();                               // §3

        // §4: WG_H updates rows 0-3 + releases cA; WG_L stores B-half staging
        if (hi) {
            float hr = bhr, hz = bhz, hn = bhn;
#pragma unroll
            for (int q = 0; q < 8; q++) {
                hr += part[(lr * 3 + 0) * 256 + q * 32 + uc];
                hz += part[(lr * 3 + 1) * 256 + q * 32 + uc];
                hn += part[(lr * 3 + 2) * 256 + q * 32 + uc];
            }
            float rgt = 1.f / (1.f + expf(-(xr + hr)));
            float zgt = 1.f / (1.f + expf(-(xz + hz)));
            float ngt = tanhf(xn + rgt * hn);
            float hp = hs[urow * 256 + cg];
            crow[(size_t)t * CC + cg] = (1.f - zgt) * ngt + zgt * hp;
            asm volatile("bar.sync 2, 128;" ::: "memory");
            if (tid == 128) rel_add(cA);
        } else if (t > 0) {
            *(float4*)&hs[(srow)*256 + scol]     = stg0;
            *(float4*)&hs[(srow)*256 + scol + 4] = stg1;
        }
        __syncthreads();                               // §5

        // §6: phase B partials (rows 4-7)
        GRU_PHASE(4);
        __syncthreads();                               // §7

        // §8: WG_L updates rows 4-7 + releases cB; WG_H stages A-half h_t
        if (!hi) {
            float hr = bhr, hz = bhz, hn = bhn;
#pragma unroll
            for (int q = 0; q < 8; q++) {
                hr += part[(lr * 3 + 0) * 256 + q * 32 + uc];
                hz += part[(lr * 3 + 1) * 256 + q * 32 + uc];
                hn += part[(lr * 3 + 2) * 256 + q * 32 + uc];
            }
            float rgt = 1.f / (1.f + expf(-(xr + hr)));
            float zgt = 1.f / (1.f + expf(-(xz + hz)));
            float ngt = tanhf(xn + rgt * hn);
            float hp = hs[urow * 256 + cg];
            crow[(size_t)t * CC + cg] = (1.f - zgt) * ngt + zgt * hp;
            asm volatile("bar.sync 1, 128;" ::: "memory");
            if (tid == 0) rel_add(cB);
        } else {
            if (tid == 128) spin_ge(cA, 8u * (unsigned)(t + 1));
            asm volatile("bar.sync 2, 128;" ::: "memory");
            const float4* s = (const float4*)(sbase + (size_t)t * CC);
            float4 a0 = __ldcg(s);
            float4 a1 = __ldcg(s + 1);
            *(float4*)&hs[srow * 256 + scol]     = a0;
            *(float4*)&hs[srow * 256 + scol + 4] = a1;
        }
        __syncthreads();                               // §9
    }
}

// ---------------- fused loss: tf32 mma, 512 threads, pipelined fragments ----------------
#define LOSS_SMEM ((128 * 132 + 128 * 132 + 128 + 64) * 4)

#define S1_LOAD(buf, k0) do { \
    _Pragma("unroll") \
    for (int mt = 0; mt < 2; mt++) { \
        int r = R0 + mt * 16 + g; \
        af[buf][mt][0] = __float_as_uint(As[r * 36 + (k0) + tq]); \
        af[buf][mt][1] = __float_as_uint(As[(r + 8) * 36 + (k0) + tq]); \
        af[buf][mt][2] = __float_as_uint(As[r * 36 + (k0) + tq + 4]); \
        af[buf][mt][3] = __float_as_uint(As[(r + 8) * 36 + (k0) + tq + 4]); \
    } \
    _Pragma("unroll") \
    for (int nt = 0; nt < 4; nt++) { \
        int c = C0 + nt * 8 + g; \
        bf[buf][nt][0] = __float_as_uint(Bs[((k0) + tq) * 136 + c]); \
        bf[buf][nt][1] = __float_as_uint(Bs[((k0) + tq + 4) * 136 + c]); \
    } \
} while (0)

#define S2_LOAD(buf, k0) do { \
    _Pragma("unroll") \
    for (int mt = 0; mt < 2; mt++) { \
        int r = R0 + mt * 16 + g; \
        af[buf][mt][0] = __float_as_uint(Psm[r * 132 + (k0) + tq]); \
        af[buf][mt][1] = __float_as_uint(Psm[(r + 8) * 132 + (k0) + tq]); \
        af[buf][mt][2] = __float_as_uint(Psm[r * 132 + (k0) + tq + 4]); \
        af[buf][mt][3] = __float_as_uint(Psm[(r + 8) * 132 + (k0) + tq + 4]); \
    } \
    _Pragma("unroll") \
    for (int nt = 0; nt < 4; nt++) { \
        int c = C0 + nt * 8 + g; \
        bf[buf][nt][0] = __float_as_uint(Zsm[c * 132 + (k0) + tq]); \
        bf[buf][nt][1] = __float_as_uint(Zsm[c * 132 + (k0) + tq + 4]); \
    } \
} while (0)

#define S_MMA(accv, buf) do { \
    _Pragma("unroll") \
    for (int mt = 0; mt < 2; mt++) \
        _Pragma("unroll") \
        for (int nt = 0; nt < 4; nt++) \
            MMA_TF32(accv[mt][nt], af[buf][mt], bf[buf][nt]); \
} while (0)

__global__ __launch_bounds__(512) void k_loss(const float* __restrict__ Wkw,
                                              const float* __restrict__ Wkb) {
    extern __shared__ float sm[];
    float* Psm = sm;                     // [128][132]
    float* As  = sm + 128 * 132;         // [128][36]
    float* Bs  = As + 128 * 36;          // [32][136]
    float* Zsm = sm + 128 * 132;         // [128][132] (aliases As/Bs)
    float* rnorm = sm + 2 * 128 * 132;
    float* red = rnorm + 128;

    int t = blockIdx.x, k = blockIdx.y;
    int tid = threadIdx.x;
    int lane = tid & 31, wid = tid >> 5;
    int g = lane >> 2, tq = lane & 3;
    int R0 = (wid >> 2) * 32;
    int C0 = (wid & 3) * 32;

    int ar[8], ak[8], bk[8], bd[8];
#pragma unroll
    for (int j = 0; j < 8; j++) {
        int i = tid + j * 512;
        ar[j] = i >> 5;  ak[j] = i & 31;
        bk[j] = i >> 7;  bd[j] = i & 127;
    }

    uint af[2][2][4], bf[2][4][2];

    float acc[2][4][4];
#pragma unroll
    for (int mt = 0; mt < 2; mt++)
#pragma unroll
        for (int nt = 0; nt < 4; nt++)
#pragma unroll
            for (int i = 0; i < 4; i++) acc[mt][nt][i] = 0.f;

    float ra[8], rb[8];
#pragma unroll
    for (int j = 0; j < 8; j++) {
        ra[j] = g_c[((size_t)ar[j] * TT + t) * CC + ak[j]];
        rb[j] = Wkw[((size_t)k * CC + bk[j]) * DD + bd[j]];
    }

    for (int kc = 0; kc < CC; kc += 32) {
#pragma unroll
        for (int j = 0; j < 8; j++) {
            As[ar[j] * 36 + ak[j]]  = __uint_as_float(f2tf(ra[j]));
            Bs[bk[j] * 136 + bd[j]] = __uint_as_float(f2tf(rb[j]));
        }
        __syncthreads();
        if (kc + 32 < CC) {
#pragma unroll
            for (int j = 0; j < 8; j++) {
                ra[j] = g_c[((size_t)ar[j] * TT + t) * CC + kc + 32 + ak[j]];
                rb[j] = Wkw[((size_t)k * CC + kc + 32 + bk[j]) * DD + bd[j]];
            }
        }
        S1_LOAD(0, 0);
        S1_LOAD(1, 8);
        S_MMA(acc, 0);
        S1_LOAD(0, 16);
        S_MMA(acc, 1);
        S1_LOAD(1, 24);
        S_MMA(acc, 0);
        S_MMA(acc, 1);
        __syncthreads();
    }

#pragma unroll
    for (int nt = 0; nt < 4; nt++) {
        int c0 = C0 + nt * 8 + 2 * tq;
        float bia0 = __ldg(&Wkb[k * DD + c0]);
        float bia1 = __ldg(&Wkb[k * DD + c0 + 1]);
#pragma unroll
        for (int mt = 0; mt < 2; mt++) {
            int r = R0 + mt * 16 + g;
            Psm[r * 132 + c0]           = __uint_as_float(f2tf(acc[mt][nt][0] + bia0));
            Psm[r * 132 + c0 + 1]       = __uint_as_float(f2tf(acc[mt][nt][1] + bia1));
            Psm[(r + 8) * 132 + c0]     = __uint_as_float(f2tf(acc[mt][nt][2] + bia0));
            Psm[(r + 8) * 132 + c0 + 1] = __uint_as_float(f2tf(acc[mt][nt][3] + bia1));
        }
    }
    __syncthreads();

    for (int i = tid; i < 16384; i += 512) {
        int cidx = i >> 7, d = i & 127;
        Zsm[cidx * 132 + d] =
            __uint_as_float(f2tf(g_z[((size_t)cidx * TT + t + k + 1) * DD + d]));
    }
    if (tid < 128) {
        const float4* pp = (const float4*)&Psm[tid * 132];
        float ss = 0.f;
#pragma unroll
        for (int q = 0; q < 32; q++) {
            float4 v = pp[q];
            ss += v.x * v.x + v.y * v.y + v.z * v.z + v.w * v.w;
        }
        rnorm[tid] = 1.f / fmaxf(sqrtf(ss), 1e-12f);
    }
    __syncthreads();

    float acc2[2][4][4];
#pragma unroll
    for (int mt = 0; mt < 2; mt++)
#pragma unroll
        for (int nt = 0; nt < 4; nt++)
#pragma unroll
            for (int i = 0; i < 4; i++) acc2[mt][nt][i] = 0.f;

    S2_LOAD(0, 0);
#pragma unroll
    for (int ks = 0; ks < 16; ks++) {
        int cur = ks & 1;
        if (ks < 15) {
            if (cur) { S2_LOAD(0, (ks + 1) * 8); }
            else     { S2_LOAD(1, (ks + 1) * 8); }
        }
        S_MMA(acc2, cur);
    }
    __syncthreads();

#pragma unroll
    for (int mt = 0; mt < 2; mt++) {
        int r = R0 + mt * 16 + g;
        float rn0 = rnorm[r] * 10.0f;
        float rn1 = rnorm[r + 8] * 10.0f;
#pragma unroll
        for (int nt = 0; nt < 4; nt++) {
            int c0 = C0 + nt * 8 + 2 * tq;
            Psm[r * 132 + c0]           = acc2[mt][nt][0] * rn0;
            Psm[r * 132 + c0 + 1]       = acc2[mt][nt][1] * rn0;
            Psm[(r + 8) * 132 + c0]     = acc2[mt][nt][2] * rn1;
            Psm[(r + 8) * 132 + c0 + 1] = acc2[mt][nt][3] * rn1;
        }
    }
    __syncthreads();

    float lossv = 0.f;
    int corr = 0;
    {
        int row = tid >> 2, sub = tid & 3;
        const float* L = &Psm[row * 132];
        int c0 = sub * 32;
        float m = -1e30f;
        int am = 0;
        for (int cc = c0; cc < c0 + 32; cc++) {
            float v = L[cc];
            if (v > m) { m = v; am = cc; }
        }
#pragma unroll
        for (int o = 1; o <= 2; o <<= 1) {
            float om = __shfl_xor_sync(0xffffffffu, m, o);
            int oa = __shfl_xor_sync(0xffffffffu, am, o);
            if (om > m || (om == m && oa < am)) { m = om; am = oa; }
        }
        float s = 0.f;
        for (int cc = c0; cc < c0 + 32; cc++) s += expf(L[cc] - m);
#pragma unroll
        for (int o = 1; o <= 2; o <<= 1) s += __shfl_xor_sync(0xffffffffu, s, o);
        if (sub == 0) {
            lossv = m + logf(s) - L[row];
            corr = (am == row) ? 1 : 0;
        }
    }
#pragma unroll
    for (int o = 16; o; o >>= 1) {
        lossv += __shfl_xor_sync(0xffffffffu, lossv, o);
        corr += __shfl_xor_sync(0xffffffffu, corr, o);
    }
    if (lane == 0) {
        red[wid] = lossv;
        ((int*)red)[16 + wid] = corr;
    }
    __syncthreads();
    if (tid == 0) {
        float s = 0.f;
        int ct = 0;
        for (int w = 0; w < 16; w++) { s += red[w]; ct += ((int*)red)[16 + w]; }
        atomicAdd(&g_loss, (double)s);
        atomicAdd(&g_cnt, ct);
    }
}

// ---------------- finalize scalars ----------------
__global__ void k_fin(float* out) {
    const double n = (double)KS * TP * BB;
    out[0] = (float)(g_loss / n);
    out[1] = (float)(100.0 * (double)g_cnt / n);
}

// ---------------- copy z_seq, c_seq into d_out ----------------
__global__ void k_copy(float* out, long long out_size) {
    size_t i0 = (size_t)blockIdx.x * blockDim.x + threadIdx.x;
    size_t stride = (size_t)gridDim.x * blockDim.x;
    const size_t NZ = (size_t)BB * TT * DD;
    const size_t NC = (size_t)BB * TT * CC;
    size_t avail = (out_size > 2) ? (size_t)(out_size - 2) : 0;
    size_t nz = NZ < avail ? NZ : avail;
    size_t nc2 = (avail > NZ) ? ((NC < avail - NZ) ? NC : avail - NZ) : 0;
    float2* oz = (float2*)(out + 2);
    const float2* z2 = (const float2*)g_z;
    for (size_t i = i0; i < nz / 2; i += stride) oz[i] = z2[i];
    float2* oc = (float2*)(out + 2 + NZ);
    const float2* c2 = (const float2*)g_c;
    for (size_t i = i0; i < nc2 / 2; i += stride) oc[i] = c2[i];
}

extern "C" void kernel_launch(void* const* d_in, const int* in_sizes, int n_in,
                              void* d_out, int out_size) {
    const float* rr  = (const float*)d_in[0];
    const float* We  = (const float*)d_in[1];
    const float* be  = (const float*)d_in[2];
    const float* Wi  = (const float*)d_in[3];
    const float* Wh  = (const float*)d_in[4];
    const float* bi  = (const float*)d_in[5];
    const float* bh  = (const float*)d_in[6];
    const float* Wkw = (const float*)d_in[7];
    const float* Wkb = (const float*)d_in[8];
    float* out = (float*)d_out;

    cudaFuncSetAttribute(k_gru4, cudaFuncAttributeMaxDynamicSharedMemorySize, GRU4_SMEM);
    cudaFuncSetAttribute(k_loss, cudaFuncAttributeMaxDynamicSharedMemorySize, LOSS_SMEM);

    k_z<<<dim3(TT / 64, BB), 128>>>(rr, We, be, Wh);      // + init + Wh transpose
    k_xproj<<<dim3(6, (BB * TT) / 128), 256>>>(Wi, bi);
    k_dummy<<<1, 32>>>();                                 // shifts ncu window onto GRU
    k_gru4<<<dim3(8, 16), 256, GRU4_SMEM>>>(bh);
    k_loss<<<dim3(TP, KS), 512, LOSS_SMEM>>>(Wkw, Wkb);
    k_fin<<<1, 1>>>(out);
    k_copy<<<2048, 256>>>(out, (long long)out_size);
}

// round 17
// speedup vs baseline: 1.0180x; 1.0180x over previous
#include <cuda_runtime.h>
#include <math.h>

#define BB 128
#define TT 512
#define WW 64
#define DD 128
#define CC 256
#define KS 12
#define TP 500

typedef unsigned long long ull;
typedef unsigned int uint;

#define NZf ((size_t)BB * TT * DD)
#define NCf ((size_t)BB * TT * CC)

// ---------------- device scratch (no runtime allocation allowed) ----------------
__device__ float g_z[(size_t)BB * TT * DD];        // 33.5 MB  (B,T,D) normalized z
__device__ float g_xp[(size_t)BB * TT * 3 * CC];   // 201 MB   (B,T,768) x_proj
__device__ float g_c[(size_t)BB * TT * CC];        // 67 MB    (B,T,C) GRU hidden states
__device__ float g_whT[3 * CC * CC];               // Wh transposed: [col][k]
__device__ double g_loss;
__device__ int    g_cnt;
__device__ unsigned g_sync[32];                    // per-rowgroup step counters

__device__ __forceinline__ uint f2tf(float f) {
    uint u;
    asm("cvt.rna.tf32.f32 %0, %1;" : "=r"(u) : "f"(f));
    return u;
}
__device__ __forceinline__ ull ffma2(ull a, ull b, ull c) {
    ull d;
    asm("fma.rn.f32x2 %0, %1, %2, %3;" : "=l"(d) : "l"(a), "l"(b), "l"(c));
    return d;
}
__device__ __forceinline__ ull packf2(float lo, float hi) {
    ull d;
    asm("mov.b64 %0, {%1, %2};" : "=l"(d) : "f"(lo), "f"(hi));
    return d;
}
__device__ __forceinline__ float pairsum(ull v) {
    float lo, hi;
    asm("mov.b64 {%0, %1}, %2;" : "=f"(lo), "=f"(hi) : "l"(v));
    return lo + hi;
}
__device__ __forceinline__ void unpackf2(ull v, float& lo, float& hi) {
    asm("mov.b64 {%0, %1}, %2;" : "=f"(lo), "=f"(hi) : "l"(v));
}
// within-8-group k permutation: pairs (tq, tq+4) become adjacent
__device__ __forceinline__ int pcol(int d) {
    return (d & ~7) | ((d & 3) << 1) | ((d >> 2) & 1);
}
#define MMA_TF32(d, a, b) \
    asm volatile("mma.sync.aligned.m16n8k8.row.col.f32.tf32.tf32.f32 " \
                 "{%0,%1,%2,%3},{%4,%5,%6,%7},{%8,%9},{%0,%1,%2,%3};" \
                 : "+f"((d)[0]), "+f"((d)[1]), "+f"((d)[2]), "+f"((d)[3]) \
                 : "r"((a)[0]), "r"((a)[1]), "r"((a)[2]), "r"((a)[3]), \
                   "r"((b)[0]), "r"((b)[1]))

// ---------------- z = l2norm(rr @ We + be)  (+ init + Wh transpose + out write) ----------------
__global__ __launch_bounds__(128) void k_z(const float* __restrict__ rr,
                                           const float* __restrict__ We,
                                           const float* __restrict__ be,
                                           const float* __restrict__ Wh,
                                           float* __restrict__ oz) {
    __shared__ float Wes[64 * 128];
    __shared__ float rs[64];
    __shared__ float red[4];
    int b = blockIdx.y;
    int t0 = blockIdx.x << 6;
    int tid = threadIdx.x;

    int gb = blockIdx.y * 8 + blockIdx.x;
    int gtid = gb * 128 + tid;
    if (gtid == 0) {
        g_loss = 0.0; g_cnt = 0;
        for (int i = 0; i < 32; i++) g_sync[i] = 0u;
    }
    for (int i = gtid; i < 3 * CC * CC; i += 131072) {
        int kk = i & 255;
        int col = i >> 8;
        g_whT[i] = Wh[(size_t)kk * 768 + col];
    }

    for (int i = tid; i < 64 * 128; i += 128) Wes[i] = We[i];
    float bias = be[tid];
    __syncthreads();
    for (int tt = 0; tt < 64; tt++) {
        int t = t0 + tt;
        if (tid < 64) rs[tid] = rr[((size_t)b * TT + t) * WW + tid];
        __syncthreads();
        float acc = bias;
#pragma unroll
        for (int w = 0; w < 64; w++) acc += rs[w] * Wes[w * 128 + tid];
        float ss = acc * acc;
#pragma unroll
        for (int o = 16; o; o >>= 1) ss += __shfl_xor_sync(0xffffffffu, ss, o);
        if ((tid & 31) == 0) red[tid >> 5] = ss;
        __syncthreads();
        float tot = red[0] + red[1] + red[2] + red[3];
        float scale = 1.0f / fmaxf(sqrtf(tot), 1e-12f);
        float zv = acc * scale;
        size_t idx = ((size_t)b * TT + t) * DD + tid;
        g_z[idx] = zv;
        if (oz) oz[idx] = zv;          // fused output write
        __syncthreads();
    }
}

// ---------------- x_proj = z @ Wi + bi  (M=65536, N=768, K=128), FFMA2 ----------------
__global__ __launch_bounds__(256) void k_xproj(const float* __restrict__ Wi,
                                               const float* __restrict__ bi) {
    __shared__ float As[32 * 132];
    __shared__ float Bs[32 * 132];
    int tid = threadIdx.x;
    int tx = tid & 15, ty = tid >> 4;
    int m0 = blockIdx.y << 7, n0 = blockIdx.x << 7;
    ull accp[8][4];
#pragma unroll
    for (int i = 0; i < 8; i++)
#pragma unroll
        for (int p = 0; p < 4; p++) accp[i][p] = 0ull;

    for (int kc = 0; kc < DD; kc += 32) {
        for (int i = tid; i < 4096; i += 256) {
            int r = i >> 5, kk = i & 31;
            As[kk * 132 + r] = g_z[(size_t)(m0 + r) * DD + kc + kk];
        }
        for (int i = tid; i < 4096; i += 256) {
            int kk = i >> 7, n = i & 127;
            Bs[kk * 132 + n] = Wi[(size_t)(kc + kk) * 768 + n0 + n];
        }
        __syncthreads();
#pragma unroll
        for (int kk = 0; kk < 32; kk++) {
            float4 a1 = *(const float4*)&As[kk * 132 + ty * 4];
            float4 a2 = *(const float4*)&As[kk * 132 + 64 + ty * 4];
            ulonglong2 B1 = *(const ulonglong2*)&Bs[kk * 132 + tx * 4];
            ulonglong2 B2 = *(const ulonglong2*)&Bs[kk * 132 + 64 + tx * 4];
            float av[8] = {a1.x, a1.y, a1.z, a1.w, a2.x, a2.y, a2.z, a2.w};
#pragma unroll
            for (int i = 0; i < 8; i++) {
                ull a2i = packf2(av[i], av[i]);
                accp[i][0] = ffma2(a2i, B1.x, accp[i][0]);
                accp[i][1] = ffma2(a2i, B1.y, accp[i][1]);
                accp[i][2] = ffma2(a2i, B2.x, accp[i][2]);
                accp[i][3] = ffma2(a2i, B2.y, accp[i][3]);
            }
        }
        __syncthreads();
    }
#pragma unroll
    for (int i = 0; i < 8; i++) {
        int r = m0 + ((i < 4) ? ty * 4 + i : 64 + ty * 4 + i - 4);
#pragma unroll
        for (int p = 0; p < 4; p++) {
            int j0 = 2 * p;
            float lo, hi;
            unpackf2(accp[i][p], lo, hi);
            int c0 = n0 + ((j0 < 4) ? tx * 4 + j0 : 64 + tx * 4 + j0 - 4);
            g_xp[(size_t)r * 768 + c0]     = lo + bi[c0];
            g_xp[(size_t)r * 768 + c0 + 1] = hi + bi[c0 + 1];
        }
    }
}

// ---------------- persistent GRU (R13 form) + fused out write ----------------
#define GRU2_SMEM ((96 * 256 + 8 * 256 + 8 * 3 * 256) * 4)
__global__ __launch_bounds__(256, 1) void k_gru2(const float* __restrict__ bh,
                                                 float* __restrict__ ocb) {
    extern __shared__ float sm[];
    float* ws   = sm;                          // [96 cols][64 float4], XOR-swizzled
    float* hs   = sm + 96 * 256;               // [8][256]   h_{t-1}
    float* part = sm + 96 * 256 + 8 * 256;     // [8][3][256] k-octant partials

    int tid = threadIdx.x;
    int cgx = blockIdx.x;
    int rg  = blockIdx.y;
    int cb0 = cgx << 5;
    int rb0 = rg << 3;

    for (int i = tid; i < 96 * 64; i += 256) {
        int bc = i >> 6, kgrp = i & 63;
        int gate = bc >> 5, ch = bc & 31;
        float4 v = *(const float4*)&g_whT[(size_t)(gate * 256 + cb0 + ch) * 256 + kgrp * 4];
        *(float4*)&ws[(bc * 64 + (kgrp ^ (bc & 7))) * 4] = v;
    }

    int uc = tid & 31;
    int kh = tid >> 5;
    int cg = cb0 + uc;
    float bhr = bh[cg], bhz = bh[256 + cg], bhn = bh[512 + cg];

    int ur = kh;
    int b  = rb0 + ur;
    const float* xpb = g_xp + (size_t)b * TT * 768;
    float* crow = g_c + (size_t)b * TT * CC;
    float* orow = ocb ? (ocb + (size_t)b * TT * CC) : (float*)0;

    int sflat = tid * 8;
    int sr = sflat >> 8, skk = sflat & 255;

    const ulonglong2* ws4 = (const ulonglong2*)ws;
    int s7 = uc & 7;
    int wb0 = (0  + uc) * 64 + kh * 8;
    int wb1 = (32 + uc) * 64 + kh * 8;
    int wb2 = (64 + uc) * 64 + kh * 8;

    for (int t = 0; t < TT; t++) {
        if (t == 0) {
            *(float4*)&hs[sflat]     = make_float4(0.f, 0.f, 0.f, 0.f);
            *(float4*)&hs[sflat + 4] = make_float4(0.f, 0.f, 0.f, 0.f);
        } else {
            const float4* s =
                (const float4*)&g_c[((size_t)(rb0 + sr) * TT + (t - 1)) * CC + skk];
            *(float4*)&hs[sflat]     = __ldcg(s);
            *(float4*)&hs[sflat + 4] = __ldcg(s + 1);
        }
        float xr = __ldg(&xpb[(size_t)t * 768 + cg]);
        float xz = __ldg(&xpb[(size_t)t * 768 + 256 + cg]);
        float xn = __ldg(&xpb[(size_t)t * 768 + 512 + cg]);
        __syncthreads();

        ull p0[8], p1[8], p2[8];
#pragma unroll
        for (int r = 0; r < 8; r++) { p0[r] = 0ull; p1[r] = 0ull; p2[r] = 0ull; }
#pragma unroll
        for (int j = 0; j < 8; j++) {
            int js = j ^ s7;
            ulonglong2 W0 = ws4[wb0 + js];
            ulonglong2 W1 = ws4[wb1 + js];
            ulonglong2 W2 = ws4[wb2 + js];
            int kofs = kh * 32 + j * 4;
#pragma unroll
            for (int r = 0; r < 8; r++) {
                ulonglong2 H = *(const ulonglong2*)&hs[r * 256 + kofs];
                p0[r] = ffma2(H.x, W0.x, p0[r]);
                p0[r] = ffma2(H.y, W0.y, p0[r]);
                p1[r] = ffma2(H.x, W1.x, p1[r]);
                p1[r] = ffma2(H.y, W1.y, p1[r]);
                p2[r] = ffma2(H.x, W2.x, p2[r]);
                p2[r] = ffma2(H.y, W2.y, p2[r]);
            }
        }
#pragma unroll
        for (int r = 0; r < 8; r++) {
            part[(r * 3 + 0) * 256 + kh * 32 + uc] = pairsum(p0[r]);
            part[(r * 3 + 1) * 256 + kh * 32 + uc] = pairsum(p1[r]);
            part[(r * 3 + 2) * 256 + kh * 32 + uc] = pairsum(p2[r]);
        }
        __syncthreads();

        {
            float hr = bhr, hz = bhz, hn = bhn;
#pragma unroll
            for (int q = 0; q < 8; q++) {
                hr += part[(ur * 3 + 0) * 256 + q * 32 + uc];
                hz += part[(ur * 3 + 1) * 256 + q * 32 + uc];
                hn += part[(ur * 3 + 2) * 256 + q * 32 + uc];
            }
            float rgt = 1.f / (1.f + expf(-(xr + hr)));
            float zgt = 1.f / (1.f + expf(-(xz + hz)));
            float ngt = tanhf(xn + rgt * hn);
            float hp = hs[ur * 256 + cg];
            float hv = (1.f - zgt) * ngt + zgt * hp;
            crow[(size_t)t * CC + cg] = hv;
            if (orow) orow[(size_t)t * CC + cg] = hv;   // fused output write
        }

        __syncthreads();
        if (tid == 0) {
            asm volatile("red.release.gpu.global.add.u32 [%0], %1;"
                         :: "l"(&g_sync[rg]), "r"(1u) : "memory");
            unsigned target = 8u * (unsigned)(t + 1);
            unsigned v;
            do {
                asm volatile("ld.acquire.gpu.u32 %0, [%1];"
                             : "=r"(v) : "l"(&g_sync[rg]) : "memory");
            } while (v < target);
        }
        __syncthreads();
    }
}

// ---------------- fused loss: tf32 mma, permuted-k layout, LDS.64 fragments ----------------
// k-dim of As/Psm/Zsm stored permuted (pcol) so fragment pairs (tq, tq+4) are
// adjacent -> LDS.64. Pitches (As 40, Psm/Zsm 136) chosen so 8B-bank index =
// 4g+tq: conflict-free per 16-lane phase. Fragment values & mma order are
// bit-identical to R15; only the rnorm summation order permutes (~1 ulp).
#define PP 136
#define AP 40
#define LOSS_SMEM ((128 * PP + 128 * PP + 128 + 64) * 4)

#define S1_LOAD(buf, k0) do { \
    _Pragma("unroll") \
    for (int mt = 0; mt < 2; mt++) { \
        int r = R0 + mt * 16 + g; \
        float2 pa = *(const float2*)&As[r * AP + (k0) + 2 * tq]; \
        float2 pb = *(const float2*)&As[(r + 8) * AP + (k0) + 2 * tq]; \
        af[buf][mt][0] = __float_as_uint(pa.x); \
        af[buf][mt][2] = __float_as_uint(pa.y); \
        af[buf][mt][1] = __float_as_uint(pb.x); \
        af[buf][mt][3] = __float_as_uint(pb.y); \
    } \
    _Pragma("unroll") \
    for (int nt = 0; nt < 4; nt++) { \
        int c = C0 + nt * 8 + g; \
        bf[buf][nt][0] = __float_as_uint(Bs[((k0) + tq) * PP + c]); \
        bf[buf][nt][1] = __float_as_uint(Bs[((k0) + tq + 4) * PP + c]); \
    } \
} while (0)

#define S2_LOAD(buf, k0) do { \
    _Pragma("unroll") \
    for (int mt = 0; mt < 2; mt++) { \
        int r = R0 + mt * 16 + g; \
        float2 pa = *(const float2*)&Psm[r * PP + (k0) + 2 * tq]; \
        float2 pb = *(const float2*)&Psm[(r + 8) * PP + (k0) + 2 * tq]; \
        af[buf][mt][0] = __float_as_uint(pa.x); \
        af[buf][mt][2] = __float_as_uint(pa.y); \
        af[buf][mt][1] = __float_as_uint(pb.x); \
        af[buf][mt][3] = __float_as_uint(pb.y); \
    } \
    _Pragma("unroll") \
    for (int nt = 0; nt < 4; nt++) { \
        float2 pz = *(const float2*)&Zsm[(C0 + nt * 8 + g) * PP + (k0) + 2 * tq]; \
        bf[buf][nt][0] = __float_as_uint(pz.x); \
        bf[buf][nt][1] = __float_as_uint(pz.y); \
    } \
} while (0)

#define S_MMA(accv, buf) do { \
    _Pragma("unroll") \
    for (int mt = 0; mt < 2; mt++) \
        _Pragma("unroll") \
        for (int nt = 0; nt < 4; nt++) \
            MMA_TF32(accv[mt][nt], af[buf][mt], bf[buf][nt]); \
} while (0)

__global__ __launch_bounds__(512) void k_loss(const float* __restrict__ Wkw,
                                              const float* __restrict__ Wkb) {
    extern __shared__ float sm[];
    float* Psm = sm;                     // [128][PP], k-dim permuted
    float* As  = sm + 128 * PP;          // [128][AP], k-dim permuted
    float* Bs  = As + 128 * AP;          // [32][PP]   (kk-major, unpermuted)
    float* Zsm = sm + 128 * PP;          // [128][PP]  (aliases As/Bs), k permuted
    float* rnorm = sm + 2 * 128 * PP;
    float* red = rnorm + 128;

    int t = blockIdx.x, k = blockIdx.y;
    int tid = threadIdx.x;
    int lane = tid & 31, wid = tid >> 5;
    int g = lane >> 2, tq = lane & 3;
    int R0 = (wid >> 2) * 32;
    int C0 = (wid & 3) * 32;

    int ar[8], akp[8], bk[8], bd[8];
#pragma unroll
    for (int j = 0; j < 8; j++) {
        int i = tid + j * 512;
        ar[j] = i >> 5;  akp[j] = pcol(i & 31);
        bk[j] = i >> 7;  bd[j] = i & 127;
    }

    uint af[2][2][4], bf[2][4][2];

    // ======== stage 1: P = c_t @ Wk[k]  (128x128, K=256), tf32 mma ========
    float acc[2][4][4];
#pragma unroll
    for (int mt = 0; mt < 2; mt++)
#pragma unroll
        for (int nt = 0; nt < 4; nt++)
#pragma unroll
            for (int i = 0; i < 4; i++) acc[mt][nt][i] = 0.f;

    float ra[8], rb[8];
#pragma unroll
    for (int j = 0; j < 8; j++) {
        ra[j] = g_c[((size_t)ar[j] * TT + t) * CC + (j * 512 + tid & 31)];
        rb[j] = Wkw[((size_t)k * CC + bk[j]) * DD + bd[j]];
    }
    // NOTE: ak logical = i & 31 == (tid + j*512) & 31 == tid & 31 (512 % 32 == 0)
    int akl = tid & 31;
#pragma unroll
    for (int j = 0; j < 8; j++)
        ra[j] = g_c[((size_t)ar[j] * TT + t) * CC + akl];

    for (int kc = 0; kc < CC; kc += 32) {
#pragma unroll
        for (int j = 0; j < 8; j++) {
            As[ar[j] * AP + akp[j]] = __uint_as_float(f2tf(ra[j]));
            Bs[bk[j] * PP + bd[j]]  = __uint_as_float(f2tf(rb[j]));
        }
        __syncthreads();
        if (kc + 32 < CC) {
#pragma unroll
            for (int j = 0; j < 8; j++) {
                ra[j] = g_c[((size_t)ar[j] * TT + t) * CC + kc + 32 + akl];
                rb[j] = Wkw[((size_t)k * CC + kc + 32 + bk[j]) * DD + bd[j]];
            }
        }
        S1_LOAD(0, 0);
        S1_LOAD(1, 8);
        S_MMA(acc, 0);
        S1_LOAD(0, 16);
        S_MMA(acc, 1);
        S1_LOAD(1, 24);
        S_MMA(acc, 0);
        S_MMA(acc, 1);
        __syncthreads();
    }

    // epilogue: +bias, round to tf32, stash into permuted Psm (stage2 A-operand)
    {
        int e0 = 2 * tq, e1 = 2 * tq + 1;
        int w0 = ((e0 & 3) << 1) | ((e0 >> 2) & 1);
        int w1 = ((e1 & 3) << 1) | ((e1 >> 2) & 1);
#pragma unroll
        for (int nt = 0; nt < 4; nt++) {
            int base = C0 + nt * 8;
            float bia0 = __ldg(&Wkb[k * DD + base + e0]);
            float bia1 = __ldg(&Wkb[k * DD + base + e1]);
#pragma unroll
            for (int mt = 0; mt < 2; mt++) {
                int r = R0 + mt * 16 + g;
                Psm[r * PP + base + w0]       = __uint_as_float(f2tf(acc[mt][nt][0] + bia0));
                Psm[r * PP + base + w1]       = __uint_as_float(f2tf(acc[mt][nt][1] + bia1));
                Psm[(r + 8) * PP + base + w0] = __uint_as_float(f2tf(acc[mt][nt][2] + bia0));
                Psm[(r + 8) * PP + base + w1] = __uint_as_float(f2tf(acc[mt][nt][3] + bia1));
            }
        }
    }
    __syncthreads();

    // load zf tile (tf32-rounded, permuted k): Z[c][pcol(d)] = z[c, t+k+1, d]
    for (int i = tid; i < 16384; i += 512) {
        int cidx = i >> 7, d = i & 127;
        Zsm[cidx * PP + pcol(d)] =
            __uint_as_float(f2tf(g_z[((size_t)cidx * TT + t + k + 1) * DD + d]));
    }
    // per-row 1/||P|| (permutation-invariant sum, order differs ~1ulp)
    if (tid < 128) {
        const float4* pp = (const float4*)&Psm[tid * PP];
        float ss = 0.f;
#pragma unroll
        for (int q = 0; q < 32; q++) {
            float4 v = pp[q];
            ss += v.x * v.x + v.y * v.y + v.z * v.z + v.w * v.w;
        }
        rnorm[tid] = 1.f / fmaxf(sqrtf(ss), 1e-12f);
    }
    __syncthreads();

    // ======== stage 2: S = P @ Z^T  (128x128, K=128), tf32 mma, pipelined ========
    float acc2[2][4][4];
#pragma unroll
    for (int mt = 0; mt < 2; mt++)
#pragma unroll
        for (int nt = 0; nt < 4; nt++)
#pragma unroll
            for (int i = 0; i < 4; i++) acc2[mt][nt][i] = 0.f;

    S2_LOAD(0, 0);
#pragma unroll
    for (int ks = 0; ks < 16; ks++) {
        int cur = ks & 1;
        if (ks < 15) {
            if (cur) { S2_LOAD(0, (ks + 1) * 8); }
            else     { S2_LOAD(1, (ks + 1) * 8); }
        }
        S_MMA(acc2, cur);
    }
    __syncthreads();   // all Psm reads done before logits overwrite

    // logits = rnorm[b] * S / TEMP  -> Psm (fp32, batch cols unpermuted)
#pragma unroll
    for (int mt = 0; mt < 2; mt++) {
        int r = R0 + mt * 16 + g;
        float rn0 = rnorm[r] * 10.0f;
        float rn1 = rnorm[r + 8] * 10.0f;
#pragma unroll
        for (int nt = 0; nt < 4; nt++) {
            int c0 = C0 + nt * 8 + 2 * tq;
            Psm[r * PP + c0]           = acc2[mt][nt][0] * rn0;
            Psm[r * PP + c0 + 1]       = acc2[mt][nt][1] * rn0;
            Psm[(r + 8) * PP + c0]     = acc2[mt][nt][2] * rn1;
            Psm[(r + 8) * PP + c0 + 1] = acc2[mt][nt][3] * rn1;
        }
    }
    __syncthreads();

    // per-row LSE, diag, argmax: 4 lanes per row
    float lossv = 0.f;
    int corr = 0;
    {
        int row = tid >> 2, sub = tid & 3;
        const float* L = &Psm[row * PP];
        int c0 = sub * 32;
        float m = -1e30f;
        int am = 0;
        for (int cc = c0; cc < c0 + 32; cc++) {
            float v = L[cc];
            if (v > m) { m = v; am = cc; }
        }
#pragma unroll
        for (int o = 1; o <= 2; o <<= 1) {
            float om = __shfl_xor_sync(0xffffffffu, m, o);
            int oa = __shfl_xor_sync(0xffffffffu, am, o);
            if (om > m || (om == m && oa < am)) { m = om; am = oa; }
        }
        float s = 0.f;
        for (int cc = c0; cc < c0 + 32; cc++) s += expf(L[cc] - m);
#pragma unroll
        for (int o = 1; o <= 2; o <<= 1) s += __shfl_xor_sync(0xffffffffu, s, o);
        if (sub == 0) {
            lossv = m + logf(s) - L[row];
            corr = (am == row) ? 1 : 0;
        }
    }
#pragma unroll
    for (int o = 16; o; o >>= 1) {
        lossv += __shfl_xor_sync(0xffffffffu, lossv, o);
        corr += __shfl_xor_sync(0xffffffffu, corr, o);
    }
    if (lane == 0) {
        red[wid] = lossv;
        ((int*)red)[16 + wid] = corr;
    }
    __syncthreads();
    if (tid == 0) {
        float s = 0.f;
        int ct = 0;
        for (int w = 0; w < 16; w++) { s += red[w]; ct += ((int*)red)[16 + w]; }
        atomicAdd(&g_loss, (double)s);
        atomicAdd(&g_cnt, ct);
    }
}

// ---------------- finalize scalars ----------------
__global__ void k_fin(float* out) {
    const double n = (double)KS * TP * BB;
    out[0] = (float)(g_loss / n);
    out[1] = (float)(100.0 * (double)g_cnt / n);
}

// ---------------- fallback copy (only if out_size mismatches fused layout) ----------------
__global__ void k_copy(float* out, long long out_size) {
    size_t i0 = (size_t)blockIdx.x * blockDim.x + threadIdx.x;
    size_t stride = (size_t)gridDim.x * blockDim.x;
    size_t avail = (out_size > 2) ? (size_t)(out_size - 2) : 0;
    size_t nz = NZf < avail ? NZf : avail;
    size_t nc2 = (avail > NZf) ? ((NCf < avail - NZf) ? NCf : avail - NZf) : 0;
    float2* oz = (float2*)(out + 2);
    const float2* z2 = (const float2*)g_z;
    for (size_t i = i0; i < nz / 2; i += stride) oz[i] = z2[i];
    float2* oc = (float2*)(out + 2 + NZf);
    const float2* c2 = (const float2*)g_c;
    for (size_t i = i0; i < nc2 / 2; i += stride) oc[i] = c2[i];
}

extern "C" void kernel_launch(void* const* d_in, const int* in_sizes, int n_in,
                              void* d_out, int out_size) {
    const float* rr  = (const float*)d_in[0];
    const float* We  = (const float*)d_in[1];
    const float* be  = (const float*)d_in[2];
    const float* Wi  = (const float*)d_in[3];
    const float* Wh  = (const float*)d_in[4];
    const float* bi  = (const float*)d_in[5];
    const float* bh  = (const float*)d_in[6];
    const float* Wkw = (const float*)d_in[7];
    const float* Wkb = (const float*)d_in[8];
    float* out = (float*)d_out;

    cudaFuncSetAttribute(k_gru2, cudaFuncAttributeMaxDynamicSharedMemorySize, GRU2_SMEM);
    cudaFuncSetAttribute(k_loss, cudaFuncAttributeMaxDynamicSharedMemorySize, LOSS_SMEM);

    bool fused = ((long long)out_size == (long long)(2 + NZf + NCf));

    k_z<<<dim3(TT / 64, BB), 128>>>(rr, We, be, Wh, fused ? out + 2 : (float*)0);
    k_xproj<<<dim3(6, (BB * TT) / 128), 256>>>(Wi, bi);
    k_gru2<<<dim3(8, 16), 256, GRU2_SMEM>>>(bh, fused ? out + 2 + NZf : (float*)0);
    k_loss<<<dim3(TP, KS), 512, LOSS_SMEM>>>(Wkw, Wkb);
    k_fin<<<1, 1>>>(out);
    if (!fused) k_copy<<<2048, 256>>>(out, (long long)out_size);
}